// round 2
// baseline (speedup 1.0000x reference)
#include <cuda_runtime.h>
#include <cuda_bf16.h>
#include <cstdint>

// ---------------------------------------------------------------------------
// Problem constants
// ---------------------------------------------------------------------------
#define BATCH   32
#define NAGENT  64
#define BN      2048            // BATCH * NAGENT
#define CIN0    16
#define HW0     30
#define FLAT    7744            // 16*22*22
#define EDIM    128
#define ADIM    5

// Conv smem ping-pong layout (floats)
#define SM_TOTAL   34176        // max(in+out) over stages = 12544 + 21632
#define OFF_IN0    0            // 16*30*30 = 14400
#define OFF_OUT0   21632        // 16*28*28 = 12544  (ends at 34176)
#define OFF_OUT1   0            // 32*26*26 = 21632
#define OFF_OUT2   24960        // 16*24*24 = 9216   (ends at 34176)
#define OFF_OUT3   0            // 16*22*22 = 7744

// ---------------------------------------------------------------------------
// Scratch (device globals: allocation-free by construction)
// ---------------------------------------------------------------------------
__device__ float g_flat [ (size_t)BN * FLAT ];   // conv features
__device__ float g_acc0 [ BN * EDIM ];           // mlp0 split-K accumulator
__device__ float g_x1   [ BN * EDIM ];
__device__ float g_feats[ BN * EDIM ];
__device__ float g_h    [ BN * EDIM ];
__device__ float g_emb  [ BN * EDIM ];
__device__ float g_q1   [ BN * EDIM ];
__device__ float g_q2   [ BN * EDIM ];

// ---------------------------------------------------------------------------
// Fused per-agent conv stack
// ---------------------------------------------------------------------------
template<int CI, int CO, int IHW, int OHW>
__device__ __forceinline__ void conv_stage(const float* __restrict__ in,
                                           float* __restrict__ out,
                                           const float* __restrict__ w,
                                           const float* __restrict__ bias,
                                           int tid, int nthr)
{
    for (int p = tid; p < CO * OHW; p += nthr) {
        int co = p / OHW;
        int y  = p - co * OHW;
        float acc[OHW];
        float bv = __ldg(&bias[co]);
        #pragma unroll
        for (int x = 0; x < OHW; x++) acc[x] = bv;

        const float* wco = w + co * (CI * 9);
        for (int ci = 0; ci < CI; ci++) {
            const float* irow = in + (ci * IHW + y) * IHW;
            const float* wp   = wco + ci * 9;
            #pragma unroll
            for (int ky = 0; ky < 3; ky++) {
                float w0 = __ldg(&wp[ky*3+0]);
                float w1 = __ldg(&wp[ky*3+1]);
                float w2 = __ldg(&wp[ky*3+2]);
                const float* r = irow + ky * IHW;
                float a0 = r[0], a1 = r[1];
                #pragma unroll
                for (int x = 0; x < OHW; x++) {
                    float a2 = r[x + 2];
                    acc[x] = fmaf(a0, w0, acc[x]);
                    acc[x] = fmaf(a1, w1, acc[x]);
                    acc[x] = fmaf(a2, w2, acc[x]);
                    a0 = a1; a1 = a2;
                }
            }
        }
        float* orow = out + p * OHW;
        #pragma unroll
        for (int x = 0; x < OHW; x++) orow[x] = fmaxf(acc[x], 0.0f);
    }
}

__global__ void conv_fused_kernel(const float* __restrict__ states,
                                  const float* __restrict__ cw0, const float* __restrict__ cb0,
                                  const float* __restrict__ cw1, const float* __restrict__ cb1,
                                  const float* __restrict__ cw2, const float* __restrict__ cb2,
                                  const float* __restrict__ cw3, const float* __restrict__ cb3,
                                  float* __restrict__ flat)
{
    extern __shared__ float s[];
    const int agent = blockIdx.x;
    const int tid = threadIdx.x, nthr = blockDim.x;

    // load input image [16,30,30]
    {
        const float4* src = (const float4*)(states + (size_t)agent * (CIN0*HW0*HW0));
        float4* dst = (float4*)(s + OFF_IN0);
        for (int i = tid; i < (CIN0*HW0*HW0)/4; i += nthr) dst[i] = src[i];
    }
    __syncthreads();
    conv_stage<16,16,30,28>(s + OFF_IN0 , s + OFF_OUT0, cw0, cb0, tid, nthr);
    __syncthreads();
    conv_stage<16,32,28,26>(s + OFF_OUT0, s + OFF_OUT1, cw1, cb1, tid, nthr);
    __syncthreads();
    conv_stage<32,16,26,24>(s + OFF_OUT1, s + OFF_OUT2, cw2, cb2, tid, nthr);
    __syncthreads();
    conv_stage<16,16,24,22>(s + OFF_OUT2, s + OFF_OUT3, cw3, cb3, tid, nthr);
    __syncthreads();
    // write flat features
    {
        float4* fo = (float4*)(flat + (size_t)agent * FLAT);
        const float4* fs = (const float4*)(s + OFF_OUT3);
        for (int i = tid; i < FLAT/4; i += nthr) fo[i] = fs[i];
    }
}

// ---------------------------------------------------------------------------
// MLP0: C[2048,128] += A[2048,7744] @ W[7744,128], split-K via fp32 atomics
// grid (KSPLIT=8, 32), block 256.  Tile 64x128, BK=8.
// ---------------------------------------------------------------------------
#define KSPLIT  8
#define KCHUNK  968   // 7744/8

__global__ void mlp0_splitk_kernel(const float* __restrict__ A,
                                   const float* __restrict__ W,
                                   float* __restrict__ Cacc)
{
    __shared__ float As[8 * 68];
    __shared__ float Ws[8 * 128];
    const int t  = threadIdx.x;
    const int kz = blockIdx.x;
    const int m0 = blockIdx.y * 64;
    const int kstart = kz * KCHUNK;
    const int tx = t & 31, ty = t >> 5;

    float acc[8][4];
    #pragma unroll
    for (int r = 0; r < 8; r++)
        #pragma unroll
        for (int c = 0; c < 4; c++) acc[r][c] = 0.f;

    for (int kk = 0; kk < KCHUNK; kk += 8) {
        __syncthreads();
        {   // A tile: 64 rows x 8 k  (2 elems/thread)
            int e = t * 2;
            int m = e >> 3, k = e & 7;
            const float* ap = A + (size_t)(m0 + m) * FLAT + kstart + kk + k;
            As[ k      * 68 + m] = ap[0];
            As[(k + 1) * 68 + m] = ap[1];
        }
        {   // W tile: 8 k x 128 cols (float4/thread)
            int e = t * 4;
            int k = e >> 7, col = e & 127;
            *(float4*)&Ws[k * 128 + col] =
                *(const float4*)&W[(size_t)(kstart + kk + k) * EDIM + col];
        }
        __syncthreads();
        #pragma unroll
        for (int k = 0; k < 8; k++) {
            float4 b  = *(float4*)&Ws[k * 128 + tx * 4];
            float4 a0 = *(float4*)&As[k * 68 + ty * 8];
            float4 a1 = *(float4*)&As[k * 68 + ty * 8 + 4];
            float av[8] = {a0.x,a0.y,a0.z,a0.w,a1.x,a1.y,a1.z,a1.w};
            float bv[4] = {b.x,b.y,b.z,b.w};
            #pragma unroll
            for (int r = 0; r < 8; r++)
                #pragma unroll
                for (int c = 0; c < 4; c++)
                    acc[r][c] = fmaf(av[r], bv[c], acc[r][c]);
        }
    }
    #pragma unroll
    for (int r = 0; r < 8; r++) {
        int m = m0 + ty * 8 + r;
        #pragma unroll
        for (int c = 0; c < 4; c++)
            atomicAdd(&Cacc[(size_t)m * EDIM + tx * 4 + c], acc[r][c]);
    }
}

// ---------------------------------------------------------------------------
// Generic [M,128] @ [128,128] GEMM, 64-row tile per CTA, full-K in smem.
// Optional input transform relu(x + inBias[k]); optional out bias / relu.
// ---------------------------------------------------------------------------
__global__ void gemm_rt_kernel(const float* __restrict__ A,
                               const float* __restrict__ W,
                               const float* __restrict__ inBias,
                               const float* __restrict__ outBias,
                               float* __restrict__ C,
                               int inRelu, int outRelu)
{
    extern __shared__ float s[];
    float* As = s;                 // [128][68] transposed (padded)
    float* Ws = s + 128 * 68;      // [128][128]
    const int t  = threadIdx.x;
    const int m0 = blockIdx.x * 64;

    // load A tile (vectorized read, transposed scatter)
    for (int idx = t; idx < 64 * 32; idx += 256) {
        int m = idx >> 5, kq = idx & 31;
        float4 v = *(const float4*)&A[(size_t)(m0 + m) * EDIM + kq * 4];
        float vv[4] = {v.x, v.y, v.z, v.w};
        #pragma unroll
        for (int j = 0; j < 4; j++) {
            int k = kq * 4 + j;
            float x = vv[j];
            if (inRelu) x = fmaxf(x + inBias[k], 0.f);
            As[k * 68 + m] = x;
        }
    }
    for (int idx = t * 4; idx < 128 * 128; idx += 1024)
        *(float4*)&Ws[idx] = *(const float4*)&W[idx];
    __syncthreads();

    const int tx = t & 31, ty = t >> 5;
    float acc[8][4];
    #pragma unroll
    for (int r = 0; r < 8; r++)
        #pragma unroll
        for (int c = 0; c < 4; c++) acc[r][c] = 0.f;

    for (int k = 0; k < 128; k++) {
        float4 b  = *(float4*)&Ws[k * 128 + tx * 4];
        float4 a0 = *(float4*)&As[k * 68 + ty * 8];
        float4 a1 = *(float4*)&As[k * 68 + ty * 8 + 4];
        float av[8] = {a0.x,a0.y,a0.z,a0.w,a1.x,a1.y,a1.z,a1.w};
        float bv[4] = {b.x,b.y,b.z,b.w};
        #pragma unroll
        for (int r = 0; r < 8; r++)
            #pragma unroll
            for (int c = 0; c < 4; c++)
                acc[r][c] = fmaf(av[r], bv[c], acc[r][c]);
    }

    #pragma unroll
    for (int r = 0; r < 8; r++) {
        int m = m0 + ty * 8 + r;
        float4 o;
        float* oo = (float*)&o;
        #pragma unroll
        for (int c = 0; c < 4; c++) {
            float v = acc[r][c];
            if (outBias) v += outBias[tx * 4 + c];
            if (outRelu) v = fmaxf(v, 0.f);
            oo[c] = v;
        }
        *(float4*)&C[(size_t)m * EDIM + tx * 4] = o;
    }
}

// ---------------------------------------------------------------------------
// GCN aggregation: per-batch 64x64 normalized adjacency times h[64,128] + gb
// ---------------------------------------------------------------------------
__global__ void gcn_kernel(const float* __restrict__ adj,
                           const float* __restrict__ h,
                           const float* __restrict__ gb,
                           float* __restrict__ emb)
{
    extern __shared__ float s[];
    float* sA   = s;                  // 64*64
    float* sh   = s + 4096;           // 64*128
    float* sdis = s + 4096 + 8192;    // 64
    const int b = blockIdx.x, t = threadIdx.x;

    for (int i = t; i < 4096; i += 256) sA[i] = adj[(size_t)b * 4096 + i];
    for (int i = t; i < 8192; i += 256) sh[i] = h[(size_t)b * 8192 + i];
    __syncthreads();

    if (t < 64) {
        float d = 0.f;
        for (int i = 0; i < 64; i++) d += sA[i * 64 + t];
        sdis[t] = (d > 0.f) ? rsqrtf(fmaxf(d, 1e-30f)) : 0.f;
    }
    __syncthreads();

    for (int i = t; i < 4096; i += 256) {
        int r = i >> 6, c = i & 63;
        sA[i] *= sdis[r] * sdis[c];
    }
    __syncthreads();

    for (int o = t; o < 8192; o += 256) {
        int j = o >> 7, d = o & 127;
        float acc = gb[d];
        #pragma unroll 8
        for (int i = 0; i < 64; i++)
            acc = fmaf(sA[i * 64 + j], sh[i * 128 + d], acc);
        emb[(size_t)b * 8192 + o] = acc;
    }
}

// ---------------------------------------------------------------------------
// Final head: q = q2 @ fw2[128,5] + fb2, zero inactive agents
// inactives arrive as int32 (harness materializes bool as int32)
// ---------------------------------------------------------------------------
__global__ void head_kernel(const float* __restrict__ q2,
                            const float* __restrict__ fw2,
                            const float* __restrict__ fb2,
                            const int* __restrict__ inact,
                            float* __restrict__ out)
{
    int row = blockIdx.x * blockDim.x + threadIdx.x;
    if (row >= BN) return;
    float acc[ADIM];
    #pragma unroll
    for (int a = 0; a < ADIM; a++) acc[a] = fb2[a];
    const float* q = q2 + (size_t)row * EDIM;
    for (int k = 0; k < EDIM; k++) {
        float v = q[k];
        #pragma unroll
        for (int a = 0; a < ADIM; a++)
            acc[a] = fmaf(v, __ldg(&fw2[k * ADIM + a]), acc[a]);
    }
    bool z = (inact[row] != 0);
    #pragma unroll
    for (int a = 0; a < ADIM; a++)
        out[(size_t)row * ADIM + a] = z ? 0.f : acc[a];
}

__global__ void zero_kernel(float* __restrict__ p, int n)
{
    int i = blockIdx.x * blockDim.x + threadIdx.x;
    if (i < n) p[i] = 0.f;
}

// ---------------------------------------------------------------------------
// Launch
// ---------------------------------------------------------------------------
extern "C" void kernel_launch(void* const* d_in, const int* in_sizes, int n_in,
                              void* d_out, int out_size)
{
    (void)in_sizes; (void)n_in; (void)out_size;
    const float* states = (const float*)d_in[0];
    const float* adj    = (const float*)d_in[1];
    const int*   inact  = (const int*)d_in[2];
    const float* cw0 = (const float*)d_in[3];  const float* cb0 = (const float*)d_in[4];
    const float* cw1 = (const float*)d_in[5];  const float* cb1 = (const float*)d_in[6];
    const float* cw2 = (const float*)d_in[7];  const float* cb2 = (const float*)d_in[8];
    const float* cw3 = (const float*)d_in[9];  const float* cb3 = (const float*)d_in[10];
    const float* mw0 = (const float*)d_in[11]; const float* mb0 = (const float*)d_in[12];
    const float* mw1 = (const float*)d_in[13]; const float* mb1 = (const float*)d_in[14];
    const float* mw2 = (const float*)d_in[15]; const float* mb2 = (const float*)d_in[16];
    const float* gw  = (const float*)d_in[17]; const float* gb  = (const float*)d_in[18];
    const float* fw0 = (const float*)d_in[19]; const float* fb0 = (const float*)d_in[20];
    const float* fw1 = (const float*)d_in[21]; const float* fb1 = (const float*)d_in[22];
    const float* fw2 = (const float*)d_in[23]; const float* fb2 = (const float*)d_in[24];
    float* out = (float*)d_out;

    // scratch pointers
    float *p_flat, *p_acc0, *p_x1, *p_feats, *p_h, *p_emb, *p_q1, *p_q2;
    cudaGetSymbolAddress((void**)&p_flat,  g_flat);
    cudaGetSymbolAddress((void**)&p_acc0,  g_acc0);
    cudaGetSymbolAddress((void**)&p_x1,    g_x1);
    cudaGetSymbolAddress((void**)&p_feats, g_feats);
    cudaGetSymbolAddress((void**)&p_h,     g_h);
    cudaGetSymbolAddress((void**)&p_emb,   g_emb);
    cudaGetSymbolAddress((void**)&p_q1,    g_q1);
    cudaGetSymbolAddress((void**)&p_q2,    g_q2);

    const int convSmem = SM_TOTAL * 4;               // 136704 B
    const int gemmSmem = (128*68 + 128*128) * 4;     // 100352 B
    const int gcnSmem  = (4096 + 8192 + 64) * 4;     // 49408 B
    cudaFuncSetAttribute(conv_fused_kernel, cudaFuncAttributeMaxDynamicSharedMemorySize, convSmem);
    cudaFuncSetAttribute(gemm_rt_kernel,    cudaFuncAttributeMaxDynamicSharedMemorySize, gemmSmem);
    cudaFuncSetAttribute(gcn_kernel,        cudaFuncAttributeMaxDynamicSharedMemorySize, gcnSmem);

    // 0) zero split-K accumulator
    zero_kernel<<<(BN*EDIM + 255)/256, 256>>>(p_acc0, BN*EDIM);

    // 1) fused conv stack -> flat features
    conv_fused_kernel<<<BN, 256, convSmem>>>(states, cw0, cb0, cw1, cb1,
                                             cw2, cb2, cw3, cb3, p_flat);

    // 2) MLP0 split-K (bias+relu folded into next GEMM's input transform)
    mlp0_splitk_kernel<<<dim3(KSPLIT, BN/64), 256>>>(p_flat, mw0, p_acc0);

    // 3) x1 = relu( relu(acc0+mb0) @ mw1 + mb1 )
    gemm_rt_kernel<<<BN/64, 256, gemmSmem>>>(p_acc0, mw1, mb0, mb1, p_x1, 1, 1);
    // 4) feats = x1 @ mw2 + mb2
    gemm_rt_kernel<<<BN/64, 256, gemmSmem>>>(p_x1, mw2, nullptr, mb2, p_feats, 0, 0);
    // 5) h = feats @ gw
    gemm_rt_kernel<<<BN/64, 256, gemmSmem>>>(p_feats, gw, nullptr, nullptr, p_h, 0, 0);
    // 6) GCN aggregation (+gb)
    gcn_kernel<<<BATCH, 256, gcnSmem>>>(adj, p_h, gb, p_emb);
    // 7) q1 = relu(emb @ fw0 + fb0)
    gemm_rt_kernel<<<BN/64, 256, gemmSmem>>>(p_emb, fw0, nullptr, fb0, p_q1, 0, 1);
    // 8) q2 = relu(q1 @ fw1 + fb1)
    gemm_rt_kernel<<<BN/64, 256, gemmSmem>>>(p_q1, fw1, nullptr, fb1, p_q2, 0, 1);
    // 9) q = q2 @ fw2 + fb2, masked
    head_kernel<<<(BN + 255)/256, 256>>>(p_q2, fw2, fb2, inact, out);
}

// round 3
// speedup vs baseline: 1.3179x; 1.3179x over previous
#include <cuda_runtime.h>
#include <cuda_bf16.h>
#include <cstdint>

// ---------------------------------------------------------------------------
// Problem constants
// ---------------------------------------------------------------------------
#define BATCH   32
#define NAGENT  64
#define BN      2048            // BATCH * NAGENT
#define CIN0    16
#define HW0     30
#define FLAT    7744            // 16*22*22
#define EDIM    128
#define ADIM    5

// Conv smem ping-pong layout (floats)
#define SM_TOTAL   34176        // max(in+out) over stages = 12544 + 21632
#define OFF_IN0    0            // 16*30*30 = 14400
#define OFF_OUT0   21632        // 16*28*28 = 12544  (ends at 34176)
#define OFF_OUT1   0            // 32*26*26 = 21632
#define OFF_OUT2   24960        // 16*24*24 = 9216   (ends at 34176)
#define OFF_OUT3   0            // 16*22*22 = 7744

#define CONV_THREADS 224

// ---------------------------------------------------------------------------
// Scratch (device globals: allocation-free by construction)
// ---------------------------------------------------------------------------
__device__ float g_flat [ (size_t)BN * FLAT ];   // conv features
__device__ float g_acc0 [ BN * EDIM ];           // mlp0 split-K accumulator

// ---------------------------------------------------------------------------
// f32x2 packed-math helpers (Blackwell FFMA2: 2x fp32 FMA throughput)
// ---------------------------------------------------------------------------
typedef unsigned long long u64;

__device__ __forceinline__ u64 pk2(float lo, float hi) {
    u64 r; asm("mov.b64 %0, {%1, %2};" : "=l"(r) : "f"(lo), "f"(hi)); return r;
}
__device__ __forceinline__ u64 pk1(float v) {
    u64 r; asm("mov.b64 %0, {%1, %1};" : "=l"(r) : "f"(v)); return r;
}
__device__ __forceinline__ u64 ffma2(u64 a, u64 b, u64 c) {
    u64 d; asm("fma.rn.f32x2 %0, %1, %2, %3;" : "=l"(d) : "l"(a), "l"(b), "l"(c));
    return d;
}
__device__ __forceinline__ void upk2(u64 v, float& lo, float& hi) {
    asm("mov.b64 {%0, %1}, %2;" : "=f"(lo), "=f"(hi) : "l"(v));
}

// ---------------------------------------------------------------------------
// Fused per-agent conv stack, packed over output-channel pairs
// ---------------------------------------------------------------------------
template<int CI, int CO, int IHW, int OHW>
__device__ __forceinline__ void conv_stage2(const float* __restrict__ in,
                                            float* __restrict__ out,
                                            const float* __restrict__ w,
                                            const float* __restrict__ bias,
                                            int tid, int nthr)
{
    constexpr int ITEMS = (CO / 2) * OHW;
    for (int p = tid; p < ITEMS; p += nthr) {
        int co2 = p / OHW;
        int y   = p - co2 * OHW;
        int co  = co2 * 2;

        u64 acc[OHW];
        u64 binit = pk2(__ldg(&bias[co]), __ldg(&bias[co + 1]));
        #pragma unroll
        for (int x = 0; x < OHW; x++) acc[x] = binit;

        const float* wA = w + (size_t)co * CI * 9;        // channel co
        const float* wB = wA + (size_t)CI * 9;            // channel co+1

        for (int ci = 0; ci < CI; ci++) {
            #pragma unroll
            for (int ky = 0; ky < 3; ky++) {
                const float* wa = wA + ci * 9 + ky * 3;
                const float* wb = wB + ci * 9 + ky * 3;
                u64 W0 = pk2(__ldg(&wa[0]), __ldg(&wb[0]));
                u64 W1 = pk2(__ldg(&wa[1]), __ldg(&wb[1]));
                u64 W2 = pk2(__ldg(&wa[2]), __ldg(&wb[2]));
                const float* r = in + (ci * IHW + y + ky) * IHW;
                u64 b0 = pk1(r[0]);
                u64 b1 = pk1(r[1]);
                #pragma unroll
                for (int x = 0; x < OHW; x++) {
                    u64 b2 = pk1(r[x + 2]);
                    acc[x] = ffma2(b0, W0, acc[x]);
                    acc[x] = ffma2(b1, W1, acc[x]);
                    acc[x] = ffma2(b2, W2, acc[x]);
                    b0 = b1; b1 = b2;
                }
            }
        }
        float* oA = out + (co * OHW + y) * OHW;
        float* oB = out + ((co + 1) * OHW + y) * OHW;
        #pragma unroll
        for (int x = 0; x < OHW; x++) {
            float lo, hi; upk2(acc[x], lo, hi);
            oA[x] = fmaxf(lo, 0.0f);
            oB[x] = fmaxf(hi, 0.0f);
        }
    }
}

__global__ __launch_bounds__(CONV_THREADS, 1)
void conv_fused_kernel(const float* __restrict__ states,
                       const float* __restrict__ cw0, const float* __restrict__ cb0,
                       const float* __restrict__ cw1, const float* __restrict__ cb1,
                       const float* __restrict__ cw2, const float* __restrict__ cb2,
                       const float* __restrict__ cw3, const float* __restrict__ cb3,
                       float* __restrict__ flat)
{
    extern __shared__ float s[];
    const int agent = blockIdx.x;
    const int tid = threadIdx.x, nthr = blockDim.x;

    // load input image [16,30,30]
    {
        const float4* src = (const float4*)(states + (size_t)agent * (CIN0*HW0*HW0));
        float4* dst = (float4*)(s + OFF_IN0);
        for (int i = tid; i < (CIN0*HW0*HW0)/4; i += nthr) dst[i] = src[i];
    }
    __syncthreads();
    conv_stage2<16,16,30,28>(s + OFF_IN0 , s + OFF_OUT0, cw0, cb0, tid, nthr);
    __syncthreads();
    conv_stage2<16,32,28,26>(s + OFF_OUT0, s + OFF_OUT1, cw1, cb1, tid, nthr);
    __syncthreads();
    conv_stage2<32,16,26,24>(s + OFF_OUT1, s + OFF_OUT2, cw2, cb2, tid, nthr);
    __syncthreads();
    conv_stage2<16,16,24,22>(s + OFF_OUT2, s + OFF_OUT3, cw3, cb3, tid, nthr);
    __syncthreads();
    // write flat features
    {
        float4* fo = (float4*)(flat + (size_t)agent * FLAT);
        const float4* fs = (const float4*)(s + OFF_OUT3);
        for (int i = tid; i < FLAT/4; i += nthr) fo[i] = fs[i];
    }
}

// ---------------------------------------------------------------------------
// MLP0: C[2048,128] += A[2048,7744] @ W[7744,128], split-K via fp32 atomics
// grid (KSPLIT=8, 32), block 256.  Tile 64x128, BK=8.  FFMA2 inner loop.
// ---------------------------------------------------------------------------
#define KSPLIT  8
#define KCHUNK  968   // 7744/8

__global__ void mlp0_splitk_kernel(const float* __restrict__ A,
                                   const float* __restrict__ W,
                                   float* __restrict__ Cacc)
{
    __shared__ float As[8 * 68];
    __shared__ float Ws[8 * 128];
    const int t  = threadIdx.x;
    const int kz = blockIdx.x;
    const int m0 = blockIdx.y * 64;
    const int kstart = kz * KCHUNK;
    const int tx = t & 31, ty = t >> 5;

    u64 acc[8][2];
    #pragma unroll
    for (int r = 0; r < 8; r++) { acc[r][0] = 0ull; acc[r][1] = 0ull; }

    for (int kk = 0; kk < KCHUNK; kk += 8) {
        __syncthreads();
        {   // A tile: 64 rows x 8 k  (2 elems/thread)
            int e = t * 2;
            int m = e >> 3, k = e & 7;
            const float* ap = A + (size_t)(m0 + m) * FLAT + kstart + kk + k;
            As[ k      * 68 + m] = ap[0];
            As[(k + 1) * 68 + m] = ap[1];
        }
        {   // W tile: 8 k x 128 cols (float4/thread)
            int e = t * 4;
            int k = e >> 7, col = e & 127;
            *(float4*)&Ws[k * 128 + col] =
                *(const float4*)&W[(size_t)(kstart + kk + k) * EDIM + col];
        }
        __syncthreads();
        #pragma unroll
        for (int k = 0; k < 8; k++) {
            u64 B0 = *(const u64*)&Ws[k * 128 + tx * 4];
            u64 B1 = *(const u64*)&Ws[k * 128 + tx * 4 + 2];
            float4 a0 = *(float4*)&As[k * 68 + ty * 8];
            float4 a1 = *(float4*)&As[k * 68 + ty * 8 + 4];
            float av[8] = {a0.x,a0.y,a0.z,a0.w,a1.x,a1.y,a1.z,a1.w};
            #pragma unroll
            for (int r = 0; r < 8; r++) {
                u64 ar = pk1(av[r]);
                acc[r][0] = ffma2(ar, B0, acc[r][0]);
                acc[r][1] = ffma2(ar, B1, acc[r][1]);
            }
        }
    }
    #pragma unroll
    for (int r = 0; r < 8; r++) {
        int m = m0 + ty * 8 + r;
        float v0, v1, v2, v3;
        upk2(acc[r][0], v0, v1);
        upk2(acc[r][1], v2, v3);
        atomicAdd(&Cacc[(size_t)m * EDIM + tx * 4 + 0], v0);
        atomicAdd(&Cacc[(size_t)m * EDIM + tx * 4 + 1], v1);
        atomicAdd(&Cacc[(size_t)m * EDIM + tx * 4 + 2], v2);
        atomicAdd(&Cacc[(size_t)m * EDIM + tx * 4 + 3], v3);
    }
}

// ---------------------------------------------------------------------------
// Fused tail: per-batch kernel doing MLP1/MLP2/GCN-lin/GCN-agg/DQN0/DQN1/head
// grid = 32 (batch), block = 256.
// smem: sX[64*128], sY[64*128], sW[128*128] (sW doubles as adj scratch)
// ---------------------------------------------------------------------------
__device__ __forceinline__ void tail_gemm(const float* __restrict__ sIn,
                                          float* __restrict__ sOut,
                                          float* __restrict__ sW,
                                          const float* __restrict__ W,
                                          const float* __restrict__ bias,
                                          int relu, int t)
{
    __syncthreads();   // prior consumers of sW / producers of sIn done
    for (int i = t * 4; i < 128 * 128; i += 1024)
        *(float4*)&sW[i] = *(const float4*)&W[i];
    __syncthreads();

    const int tx = t & 31, ty = t >> 5;
    u64 acc[8][2];
    u64 b0i = bias ? pk2(bias[tx*4+0], bias[tx*4+1]) : 0ull;
    u64 b1i = bias ? pk2(bias[tx*4+2], bias[tx*4+3]) : 0ull;
    #pragma unroll
    for (int r = 0; r < 8; r++) { acc[r][0] = b0i; acc[r][1] = b1i; }

    #pragma unroll 4
    for (int k = 0; k < 128; k++) {
        u64 B0 = *(const u64*)&sW[k * 128 + tx * 4];
        u64 B1 = *(const u64*)&sW[k * 128 + tx * 4 + 2];
        #pragma unroll
        for (int r = 0; r < 8; r++) {
            u64 ar = pk1(sIn[(ty * 8 + r) * 128 + k]);
            acc[r][0] = ffma2(ar, B0, acc[r][0]);
            acc[r][1] = ffma2(ar, B1, acc[r][1]);
        }
    }
    #pragma unroll
    for (int r = 0; r < 8; r++) {
        float v[4];
        upk2(acc[r][0], v[0], v[1]);
        upk2(acc[r][1], v[2], v[3]);
        #pragma unroll
        for (int c = 0; c < 4; c++)
            if (relu) v[c] = fmaxf(v[c], 0.0f);
        *(float4*)&sOut[(ty * 8 + r) * 128 + tx * 4] = *(float4*)v;
    }
}

__global__ __launch_bounds__(256, 1)
void tail_fused_kernel(const float* __restrict__ acc0,
                       const float* __restrict__ mb0,
                       const float* __restrict__ mw1, const float* __restrict__ mb1,
                       const float* __restrict__ mw2, const float* __restrict__ mb2,
                       const float* __restrict__ gw,  const float* __restrict__ gb,
                       const float* __restrict__ fw0, const float* __restrict__ fb0,
                       const float* __restrict__ fw1, const float* __restrict__ fb1,
                       const float* __restrict__ fw2, const float* __restrict__ fb2,
                       const float* __restrict__ adj,
                       const int* __restrict__ inact,
                       float* __restrict__ out)
{
    extern __shared__ float s[];
    float* sX = s;            // 64*128
    float* sY = s + 8192;     // 64*128
    float* sW = s + 16384;    // 128*128 ; also adj(4096)+dis(64) scratch
    const int b = blockIdx.x, t = threadIdx.x;
    const size_t row0 = (size_t)b * NAGENT;

    // x1 input: relu(acc0 + mb0)
    for (int i = t; i < 8192; i += 256) {
        int k = i & 127;
        sX[i] = fmaxf(acc0[row0 * EDIM + i] + mb0[k], 0.0f);
    }

    tail_gemm(sX, sY, sW, mw1, mb1, 1, t);   // x1   = relu(. @ mw1 + mb1)
    tail_gemm(sY, sX, sW, mw2, mb2, 0, t);   // feats=       . @ mw2 + mb2
    tail_gemm(sX, sY, sW, gw,  nullptr, 0, t); // h  =       . @ gw

    // ---- GCN aggregation: emb[j][d] = sum_i norm[i][j] h[i][d] + gb[d] ----
    __syncthreads();
    for (int i = t; i < 4096; i += 256) sW[i] = adj[(size_t)b * 4096 + i];
    __syncthreads();
    if (t < 64) {
        float d = 0.f;
        for (int i = 0; i < 64; i++) d += sW[i * 64 + t];
        sW[4096 + t] = (d > 0.f) ? rsqrtf(fmaxf(d, 1e-30f)) : 0.f;
    }
    __syncthreads();
    for (int i = t; i < 4096; i += 256) {
        int r = i >> 6, c = i & 63;
        sW[i] *= sW[4096 + r] * sW[4096 + c];
    }
    __syncthreads();
    for (int o = t; o < 8192; o += 256) {
        int j = o >> 7, d = o & 127;
        float a = gb[d];
        #pragma unroll 8
        for (int i = 0; i < 64; i++)
            a = fmaf(sW[i * 64 + j], sY[i * 128 + d], a);
        sX[o] = a;
    }

    tail_gemm(sX, sY, sW, fw0, fb0, 1, t);   // q1 = relu(emb @ fw0 + fb0)
    tail_gemm(sY, sX, sW, fw1, fb1, 1, t);   // q2 = relu(q1  @ fw1 + fb1)

    // ---- head: q = q2 @ fw2[128,5] + fb2, masked ----
    __syncthreads();
    for (int p = t; p < NAGENT * ADIM; p += 256) {
        int row = p / ADIM, a = p - row * ADIM;
        float acc = fb2[a];
        #pragma unroll 8
        for (int k = 0; k < EDIM; k++)
            acc = fmaf(sX[row * 128 + k], __ldg(&fw2[k * ADIM + a]), acc);
        bool z = (inact[row0 + row] != 0);
        out[(row0 + row) * ADIM + a] = z ? 0.f : acc;
    }
}

__global__ void zero_kernel(float* __restrict__ p, int n)
{
    int i = blockIdx.x * blockDim.x + threadIdx.x;
    if (i < n) p[i] = 0.f;
}

// ---------------------------------------------------------------------------
// Launch
// ---------------------------------------------------------------------------
extern "C" void kernel_launch(void* const* d_in, const int* in_sizes, int n_in,
                              void* d_out, int out_size)
{
    (void)in_sizes; (void)n_in; (void)out_size;
    const float* states = (const float*)d_in[0];
    const float* adj    = (const float*)d_in[1];
    const int*   inact  = (const int*)d_in[2];
    const float* cw0 = (const float*)d_in[3];  const float* cb0 = (const float*)d_in[4];
    const float* cw1 = (const float*)d_in[5];  const float* cb1 = (const float*)d_in[6];
    const float* cw2 = (const float*)d_in[7];  const float* cb2 = (const float*)d_in[8];
    const float* cw3 = (const float*)d_in[9];  const float* cb3 = (const float*)d_in[10];
    const float* mw0 = (const float*)d_in[11]; const float* mb0 = (const float*)d_in[12];
    const float* mw1 = (const float*)d_in[13]; const float* mb1 = (const float*)d_in[14];
    const float* mw2 = (const float*)d_in[15]; const float* mb2 = (const float*)d_in[16];
    const float* gw  = (const float*)d_in[17]; const float* gb  = (const float*)d_in[18];
    const float* fw0 = (const float*)d_in[19]; const float* fb0 = (const float*)d_in[20];
    const float* fw1 = (const float*)d_in[21]; const float* fb1 = (const float*)d_in[22];
    const float* fw2 = (const float*)d_in[23]; const float* fb2 = (const float*)d_in[24];
    float* out = (float*)d_out;

    float *p_flat, *p_acc0;
    cudaGetSymbolAddress((void**)&p_flat, g_flat);
    cudaGetSymbolAddress((void**)&p_acc0, g_acc0);

    const int convSmem = SM_TOTAL * 4;                       // 136704 B
    const int tailSmem = (8192 + 8192 + 16384) * 4;          // 131072 B
    cudaFuncSetAttribute(conv_fused_kernel, cudaFuncAttributeMaxDynamicSharedMemorySize, convSmem);
    cudaFuncSetAttribute(tail_fused_kernel, cudaFuncAttributeMaxDynamicSharedMemorySize, tailSmem);

    // 0) zero split-K accumulator
    zero_kernel<<<(BN*EDIM + 255)/256, 256>>>(p_acc0, BN*EDIM);

    // 1) fused conv stack -> flat features
    conv_fused_kernel<<<BN, CONV_THREADS, convSmem>>>(states, cw0, cb0, cw1, cb1,
                                                      cw2, cb2, cw3, cb3, p_flat);

    // 2) MLP0 split-K (bias folded into tail input transform)
    mlp0_splitk_kernel<<<dim3(KSPLIT, BN/64), 256>>>(p_flat, mw0, p_acc0);

    // 3) everything else, fused per batch
    tail_fused_kernel<<<BATCH, 256, tailSmem>>>(p_acc0, mb0, mw1, mb1, mw2, mb2,
                                                gw, gb, fw0, fb0, fw1, fb1,
                                                fw2, fb2, adj, inact, out);
}